// round 10
// baseline (speedup 1.0000x reference)
#include <cuda_runtime.h>
#include <cstdint>

// Problem constants
#define NGEN  10
#define BATCH 4096
#define NZ    128
#define HID1  512
#define HID2  1024
#define IMG   784

// GEMM tiling: TM=64 x TN=128, 128 threads, 8x8 outputs/thread
#define TM 64
#define TN 128
#define TK 16
#define MAX_TILES (BATCH / TM + NGEN)   // 74

// ---------------- device scratch (no allocations allowed) ----------------
__device__ int   d_off[NGEN + 1];
__device__ int   d_tileOff[NGEN + 1];
__device__ int   d_perm[BATCH];
__device__ float d_h1[BATCH * HID1];   // 8 MB,  permuted row order
__device__ float d_h2[BATCH * HID2];   // 16 MB, permuted row order

// ---------------- fused grouping: count + scan + scatter, one block ------
#define GT 512
__global__ void k_group(const int* __restrict__ gi) {
    __shared__ int s_cnt[NGEN];
    __shared__ int s_cur[NGEN];
    const int t = threadIdx.x;
    if (t < NGEN) s_cnt[t] = 0;
    __syncthreads();
    int gloc[BATCH / GT];
#pragma unroll
    for (int r = 0; r < BATCH / GT; r++) {
        gloc[r] = gi[t + GT * r];
        atomicAdd(&s_cnt[gloc[r]], 1);
    }
    __syncthreads();
    if (t == 0) {
        int s = 0, tile = 0;
        for (int g = 0; g < NGEN; g++) {
            d_off[g] = s; d_tileOff[g] = tile; s_cur[g] = s;
            s += s_cnt[g];
            tile += (s_cnt[g] + TM - 1) / TM;
        }
        d_off[NGEN] = s; d_tileOff[NGEN] = tile;
    }
    __syncthreads();
    // order within a group is irrelevant: each sample's row computation is
    // independent and scattered back to its original row => bitwise-stable.
#pragma unroll
    for (int r = 0; r < BATCH / GT; r++) {
        int p = atomicAdd(&s_cur[gloc[r]], 1);
        d_perm[p] = t + GT * r;
    }
}

// ---------------- packed fp32x2 / async helpers ----------------
__device__ __forceinline__ unsigned long long fma2(unsigned long long a,
                                                   unsigned long long b,
                                                   unsigned long long c) {
    unsigned long long d;
    asm("fma.rn.f32x2 %0, %1, %2, %3;" : "=l"(d) : "l"(a), "l"(b), "l"(c));
    return d;
}

__device__ __forceinline__ unsigned long long dup2(float f) {
    unsigned int u = __float_as_uint(f);
    return ((unsigned long long)u << 32) | (unsigned long long)u;
}

__device__ __forceinline__ float fast_tanh(float x) {
    float y;
    asm("tanh.approx.f32 %0, %1;" : "=f"(y) : "f"(x));
    return y;
}

__device__ __forceinline__ void cp16(uint32_t dst, const float* src, bool pred) {
    int sz = pred ? 16 : 0;   // src_size=0 -> 16B zero-fill, no gmem read
    asm volatile("cp.async.cg.shared.global [%0], [%1], 16, %2;"
                 :: "r"(dst), "l"(src), "r"(sz));
}
__device__ __forceinline__ void cp_commit() {
    asm volatile("cp.async.commit_group;");
}
__device__ __forceinline__ void cp_wait0() {
    asm volatile("cp.async.wait_group 0;");
}

// ---------------- grouped SGEMM: double-buffered, cp.async B ----------------
// LAYER 1: A = gather(z via perm), C = d_h1, relu
// LAYER 2: A = d_h1,               C = d_h2, relu
// LAYER 3: A = d_h2,               C = scatter(out via perm), tanh
template <int K, int N, int LAYER>
__global__ __launch_bounds__(128, 5)
void gemm_kernel(const float* __restrict__ Ain,
                 const float* __restrict__ W,
                 const float* __restrict__ bias,
                 float* __restrict__ Cout) {
    constexpr int ASTR = 2 * TM + 2;                  // 130 floats (dup A + pad)
    constexpr int NC   = K / TK;                      // k-chunks (8/32/64)
    __shared__ __align__(16) float As[2][TK][ASTR];   // A duplicated (a,a)
    __shared__ __align__(16) float Bs[2][TK][TN];     // B verbatim K-major

    const int bx = blockIdx.x;
    if (bx >= d_tileOff[NGEN]) return;

    int g = 0;
#pragma unroll
    for (int i = 1; i < NGEN; i++)
        if (d_tileOff[i] <= bx) g = i;

    const int m_base = d_off[g] + (bx - d_tileOff[g]) * TM;
    const int m_end  = d_off[g + 1];
    const int n0     = blockIdx.y * TN;

    const float* A = (LAYER == 1) ? Ain : (LAYER == 2 ? d_h1 : d_h2);
    float*       C = (LAYER == 3) ? Cout : (LAYER == 1 ? d_h1 : d_h2);
    const float* Wg = W + (size_t)g * K * N;
    const float* bg = bias + g * N;

    const int tid = threadIdx.x;
    const int tx  = tid & 15;        // 0..15 (column groups)
    const int ty  = tid >> 4;        // 0..7  (row groups of 8)

    // ---- A tile load mapping: 2 float4/thread; rows ra0, ra0+32 ----
    const int ra0 = tid >> 2;        // 0..31
    const int c4  = tid & 3;         // k sub-chunk
    const float* aRow0 = nullptr;
    const float* aRow1 = nullptr;
    {
        int m0 = m_base + ra0;
        int m1 = m_base + ra0 + 32;
        if (m0 < m_end) {
            long s = (LAYER == 1) ? (long)d_perm[m0] : (long)m0;
            aRow0 = A + s * (long)K + c4 * 4;
        }
        if (m1 < m_end) {
            long s = (LAYER == 1) ? (long)d_perm[m1] : (long)m1;
            aRow1 = A + s * (long)K + c4 * 4;
        }
    }

    // ---- B tile cp.async mapping: 4 float4/thread ----
    // row r = (tid>>5) + 4q (q=0..3), float4-col = tid&31  (TN=128 -> 32 f4)
    const int bf4  = tid & 31;
    const int br0  = tid >> 5;       // 0..3
    const bool bok = (N % TN == 0) || (n0 + bf4 * 4 < N);  // N%4==0 -> whole f4
    const float* bSrc = Wg + (size_t)br0 * N + n0 + bf4 * 4;  // + k0*N + 4q*N
    uint32_t bDst[2];
    bDst[0] = (uint32_t)__cvta_generic_to_shared(&Bs[0][br0][bf4 * 4]);
    bDst[1] = (uint32_t)__cvta_generic_to_shared(&Bs[1][br0][bf4 * 4]);

    auto cpB = [&](int k0, int st) {
#pragma unroll
        for (int q = 0; q < 4; q++)
            cp16(bDst[st] + q * 4 * TN * 4,
                 bSrc + (size_t)(k0 + 4 * q) * N, bok);
        cp_commit();
    };

    float4 a0, a1;
    auto ldgA = [&](int k0) {
        const float4 z4 = make_float4(0.f, 0.f, 0.f, 0.f);
        a0 = z4; a1 = z4;
        if (aRow0) a0 = *reinterpret_cast<const float4*>(aRow0 + k0);
        if (aRow1) a1 = *reinterpret_cast<const float4*>(aRow1 + k0);
    };
    auto stsA = [&](int st) {
        const float* av = reinterpret_cast<const float*>(&a0);
#pragma unroll
        for (int u = 0; u < 4; u++)
            *reinterpret_cast<unsigned long long*>(&As[st][c4 * 4 + u][2 * ra0]) = dup2(av[u]);
        av = reinterpret_cast<const float*>(&a1);
#pragma unroll
        for (int u = 0; u < 4; u++)
            *reinterpret_cast<unsigned long long*>(&As[st][c4 * 4 + u][2 * (ra0 + 32)]) = dup2(av[u]);
    };

    // Accumulators: 8 rows x 4 column-pairs
    unsigned long long acc[8][4];
#pragma unroll
    for (int i = 0; i < 8; i++)
#pragma unroll
        for (int j = 0; j < 4; j++) acc[i][j] = 0ull;

    // ---- prologue: fill stage 0, prefetch chunk 1's A into regs ----
    ldgA(0);
    stsA(0);
    cpB(0, 0);
    ldgA(TK);                      // NC >= 8 always
    cp_wait0();
    __syncthreads();

    // ---- main loop: one barrier + one wait per chunk ----
#pragma unroll 1
    for (int ci = 0; ci < NC; ci++) {
        const int cur = ci & 1, nxt = cur ^ 1;
        const bool more = (ci + 1 < NC);
        if (more) {
            stsA(nxt);             // regs hold chunk ci+1
            cpB((ci + 1) * TK, nxt);
        }

#pragma unroll
        for (int kk = 0; kk < TK; kk++) {
            unsigned long long ar[8], br[4];
#pragma unroll
            for (int i = 0; i < 8; i++)   // 2 distinct addrs/warp (broadcast)
                ar[i] = *reinterpret_cast<const unsigned long long*>(&As[cur][kk][2 * (ty * 8 + i)]);
#pragma unroll
            for (int j = 0; j < 4; j++)   // 16 distinct 8B, 2-way broadcast
                br[j] = *reinterpret_cast<const unsigned long long*>(&Bs[cur][kk][2 * (tx + 16 * j)]);
#pragma unroll
            for (int i = 0; i < 8; i++)
#pragma unroll
                for (int j = 0; j < 4; j++)
                    acc[i][j] = fma2(ar[i], br[j], acc[i][j]);
        }

        if (more) {
            if (ci + 2 < NC) ldgA((ci + 2) * TK);
            cp_wait0();
            __syncthreads();
        }
    }

    // ---- epilogue: bias + activation + store (float2 per pair) ----
#pragma unroll
    for (int j = 0; j < 4; j++) {
        const int n = n0 + 2 * (tx + 16 * j);
        const bool nok = (N % TN == 0) || (n < N);   // N even: n, n+1 together
        float bv0 = 0.f, bv1 = 0.f;
        if (nok) { bv0 = bg[n]; bv1 = bg[n + 1]; }
#pragma unroll
        for (int i = 0; i < 8; i++) {
            const int m = m_base + ty * 8 + i;
            if (m >= m_end || !nok) continue;
            float v0 = __uint_as_float((unsigned int)(acc[i][j])) + bv0;
            float v1 = __uint_as_float((unsigned int)(acc[i][j] >> 32)) + bv1;
            if (LAYER == 3) { v0 = fast_tanh(v0); v1 = fast_tanh(v1); }
            else            { v0 = fmaxf(v0, 0.f); v1 = fmaxf(v1, 0.f); }
            const long r = (LAYER == 3) ? (long)d_perm[m] : (long)m;
            *reinterpret_cast<float2*>(&C[r * (long)N + n]) = make_float2(v0, v1);
        }
    }
}

// ---------------- launch ----------------
extern "C" void kernel_launch(void* const* d_in, const int* in_sizes, int n_in,
                              void* d_out, int out_size) {
    const float* z  = (const float*)d_in[0];
    const int*   gi = (const int*)  d_in[1];
    const float* W1 = (const float*)d_in[2];
    const float* b1 = (const float*)d_in[3];
    const float* W2 = (const float*)d_in[4];
    const float* b2 = (const float*)d_in[5];
    const float* W3 = (const float*)d_in[6];
    const float* b3 = (const float*)d_in[7];
    float* out = (float*)d_out;

    k_group<<<1, GT>>>(gi);

    dim3 blk(128);
    gemm_kernel<NZ,   HID1, 1><<<dim3(MAX_TILES, HID1 / TN), blk>>>(z,       W1, b1, nullptr);
    gemm_kernel<HID1, HID2, 2><<<dim3(MAX_TILES, HID2 / TN), blk>>>(nullptr, W2, b2, nullptr);
    gemm_kernel<HID2, IMG,  3><<<dim3(MAX_TILES, (IMG + TN - 1) / TN), blk>>>(nullptr, W3, b3, out);
}

// round 14
// speedup vs baseline: 1.7593x; 1.7593x over previous
#include <cuda_runtime.h>
#include <cuda_bf16.h>
#include <cstdint>

// Problem constants
#define NGEN  10
#define BATCH 4096
#define NZ    128
#define H1    512
#define H2    1024
#define IMG   784
#define IMGP  896          // IMG padded to 128

// Tiling
#define TM 128             // m rows per CTA
#define TN 128             // n cols per CTA
#define KC 32              // k per chunk (bf16); row = 64B hi + 64B lo
#define MAXT (BATCH / TM + NGEN)        // 42
#define STAGE_BYTES 32768               // A 16KB + B 16KB
#define SMEM_DYN (2 * STAGE_BYTES + 1024)

// ---------------- device scratch (no allocations; 16B-aligned) ----------------
__device__ int d_off[NGEN + 1];
__device__ int d_tileOff[NGEN + 1];
__device__ int d_perm[BATCH];

__device__ __align__(16) __nv_bfloat16 d_zH[BATCH * NZ],        d_zL[BATCH * NZ];
__device__ __align__(16) __nv_bfloat16 d_w1H[NGEN * H1 * NZ],   d_w1L[NGEN * H1 * NZ];
__device__ __align__(16) __nv_bfloat16 d_w2H[NGEN * H2 * H1],   d_w2L[NGEN * H2 * H1];
__device__ __align__(16) __nv_bfloat16 d_w3H[NGEN * IMGP * H2], d_w3L[NGEN * IMGP * H2];
__device__ __align__(16) __nv_bfloat16 d_h1H[BATCH * H1],       d_h1L[BATCH * H1];
__device__ __align__(16) __nv_bfloat16 d_h2H[BATCH * H2],       d_h2L[BATCH * H2];

// ---------------- helpers ----------------
__device__ __forceinline__ uint32_t s2u(const void* p) {
    uint32_t a;
    asm("{ .reg .u64 t; cvta.to.shared.u64 t, %1; cvt.u32.u64 %0, t; }"
        : "=r"(a) : "l"(p));
    return a;
}

__device__ __forceinline__ void cp16(uint32_t dst, const void* src, bool p) {
    int sz = p ? 16 : 0;   // src_size=0 -> zero-fill, no gmem read
    asm volatile("cp.async.cg.shared.global [%0], [%1], 16, %2;"
                 :: "r"(dst), "l"(src), "r"(sz));
}

__device__ __forceinline__ uint32_t sw(uint32_t o) {   // SW128 xor swizzle
    return o ^ ((o >> 3) & 0x70);
}

__device__ __forceinline__ void ldsm4(uint32_t* r, uint32_t a) {
    asm volatile("ldmatrix.sync.aligned.m8n8.x4.shared.b16 {%0,%1,%2,%3}, [%4];"
                 : "=r"(r[0]), "=r"(r[1]), "=r"(r[2]), "=r"(r[3]) : "r"(a));
}

__device__ __forceinline__ void hmma(float* d, const uint32_t* a,
                                     const uint32_t* b) {
    asm volatile(
        "mma.sync.aligned.m16n8k16.row.col.f32.bf16.bf16.f32 "
        "{%0,%1,%2,%3}, {%4,%5,%6,%7}, {%8,%9}, {%0,%1,%2,%3};"
        : "+f"(d[0]), "+f"(d[1]), "+f"(d[2]), "+f"(d[3])
        : "r"(a[0]), "r"(a[1]), "r"(a[2]), "r"(a[3]), "r"(b[0]), "r"(b[1]));
}

__device__ __forceinline__ float fast_tanh(float x) {
    float y; asm("tanh.approx.f32 %0, %1;" : "=f"(y) : "f"(x)); return y;
}

// ---------------- grouping: count + scan + scatter ----------------
#define GT 512
__global__ void k_group(const int* __restrict__ gi) {
    __shared__ int s_cnt[NGEN];
    __shared__ int s_cur[NGEN];
    const int t = threadIdx.x;
    if (t < NGEN) s_cnt[t] = 0;
    __syncthreads();
    int gloc[BATCH / GT];
#pragma unroll
    for (int r = 0; r < BATCH / GT; r++) {
        gloc[r] = gi[t + GT * r];
        atomicAdd(&s_cnt[gloc[r]], 1);
    }
    __syncthreads();
    if (t == 0) {
        int s = 0, tile = 0;
        for (int g = 0; g < NGEN; g++) {
            d_off[g] = s; d_tileOff[g] = tile; s_cur[g] = s;
            s += s_cnt[g];
            tile += (s_cnt[g] + TM - 1) / TM;
        }
        d_off[NGEN] = s; d_tileOff[NGEN] = tile;
    }
    __syncthreads();
#pragma unroll
    for (int r = 0; r < BATCH / GT; r++) {
        int p = atomicAdd(&s_cur[gloc[r]], 1);
        d_perm[p] = t + GT * r;   // per-row output independent => order-stable
    }
}

// ---------------- prep: z -> bf16 hi/lo ----------------
__global__ void k_convZ(const float* __restrict__ z) {
    int i = blockIdx.x * 256 + threadIdx.x;
    float v = z[i];
    __nv_bfloat16 h = __float2bfloat16(v);
    d_zH[i] = h;
    d_zL[i] = __float2bfloat16(v - __bfloat162float(h));
}

// ---------------- prep: W[k][n] -> Wt_hi/lo[n][k] (transpose + split) ----
// Destinations selected by WSEL in DEVICE code (device symbols are not valid
// as host-side kernel arguments!).
template <int K, int N, int NPAD, int WSEL>
__global__ void k_convW(const float* __restrict__ W) {
    __nv_bfloat16* Th = (WSEL == 1) ? d_w1H : (WSEL == 2) ? d_w2H : d_w3H;
    __nv_bfloat16* Tl = (WSEL == 1) ? d_w1L : (WSEL == 2) ? d_w2L : d_w3L;
    __shared__ float tile[32][33];
    const int g  = blockIdx.z;
    const int n0 = blockIdx.x * 32;
    const int k0 = blockIdx.y * 32;
    const int tx = threadIdx.x, ty = threadIdx.y;
    const float* Wg = W + (size_t)g * K * N;
#pragma unroll
    for (int i = 0; i < 4; i++) {
        int k = k0 + ty + 8 * i;
        float v = (n0 + tx < N) ? Wg[(size_t)k * N + n0 + tx] : 0.f;
        tile[ty + 8 * i][tx] = v;
    }
    __syncthreads();
#pragma unroll
    for (int i = 0; i < 4; i++) {
        int r = ty + 8 * i;                 // local n
        float v = tile[tx][r];              // = W[k0+tx][n0+r]
        __nv_bfloat16 h = __float2bfloat16(v);
        size_t o = ((size_t)g * NPAD + n0 + r) * K + k0 + tx;
        Th[o] = h;
        Tl[o] = __float2bfloat16(v - __bfloat162float(h));
    }
}

// ---------------- grouped bf16 warp-MMA GEMM (3-term split) ----------------
// D[m][n] = sum_k A[m][k]*Wt[n][k]; warp tile 64x32 (4x4 m16n8k16 frags)
// All scratch arrays resolved from LAYER in device code.
template <int K, int NOUT, int NPAD, int LAYER>
__global__ __launch_bounds__(256, 2)
void mma_kernel(const float* __restrict__ bias,
                float* __restrict__ out) {
    const __nv_bfloat16* Ahi = (LAYER == 1) ? d_zH : (LAYER == 2) ? d_h1H : d_h2H;
    const __nv_bfloat16* Alo = (LAYER == 1) ? d_zL : (LAYER == 2) ? d_h1L : d_h2L;
    const __nv_bfloat16* Bhi = (LAYER == 1) ? d_w1H : (LAYER == 2) ? d_w2H : d_w3H;
    const __nv_bfloat16* Blo = (LAYER == 1) ? d_w1L : (LAYER == 2) ? d_w2L : d_w3L;
    __nv_bfloat16* Chi = (LAYER == 1) ? d_h1H : d_h2H;   // unused for LAYER 3
    __nv_bfloat16* Clo = (LAYER == 1) ? d_h1L : d_h2L;

    extern __shared__ char dyn[];
    const uint32_t pb = (s2u(dyn) + 1023u) & ~1023u;

    const int bx = blockIdx.x;
    if (bx >= d_tileOff[NGEN]) return;
    int g = 0;
#pragma unroll
    for (int i = 1; i < NGEN; i++)
        if (d_tileOff[i] <= bx) g = i;
    const int m_base = d_off[g] + (bx - d_tileOff[g]) * TM;
    const int m_end  = d_off[g + 1];
    const int n0     = blockIdx.y * TN;

    const int tid  = threadIdx.x;
    const int lane = tid & 31, wid = tid >> 5;
    const int wm   = wid & 1;        // m half (0/1): rows wm*64
    const int wn   = wid >> 1;       // n quarter (0..3): cols wn*32

    // ---- cp.async source mapping: thread t -> tile row t>>1, half t&1 ----
    const int  crow = tid >> 1;
    const int  half = tid & 1;       // 0 = hi bytes [0,64), 1 = lo bytes [64,128)
    bool pA = false;
    const __nv_bfloat16* aSrc = Ahi;
    { int m = m_base + crow;
      if (m < m_end) { pA = true;
          long r = (LAYER == 1) ? (long)d_perm[m] : (long)m;
          aSrc = (half ? Alo : Ahi) + r * (long)K; } }
    const __nv_bfloat16* bSrc =
        (half ? Blo : Bhi) + ((size_t)g * NPAD + n0 + crow) * K;
    const uint32_t dstBase = crow * 128 + half * 64;

    auto ldchunk = [&](int kof, int st) {
        const uint32_t sA = pb + st * STAGE_BYTES;
        const uint32_t sB = sA + 16384;
#pragma unroll
        for (int q = 0; q < 4; q++) {
            uint32_t o = sw(dstBase + q * 16);
            cp16(sA + o, aSrc + kof + q * 8, pA);
            cp16(sB + o, bSrc + kof + q * 8, true);
        }
        asm volatile("cp.async.commit_group;" ::: "memory");
    };

    // ---- accumulators: 4 mfrags x 4 nfrags x 4 floats ----
    float acc[4][4][4];
#pragma unroll
    for (int i = 0; i < 4; i++)
#pragma unroll
        for (int j = 0; j < 4; j++)
#pragma unroll
            for (int c = 0; c < 4; c++) acc[i][j][c] = 0.f;

    // ldmatrix lane address components (within-tile)
    const int aRowL = wm * 64 + (lane & 7) + 8 * ((lane >> 3) & 1); // + i*16
    const int aKL   = (lane >> 4) * 16;                             // + ks*32
    const int bRowL = wn * 32 + (lane >> 4) * 8 + (lane & 7);       // + jp*16
    const int bKL   = ((lane >> 3) & 1) * 16;                       // + ks*32

    const int NC = K / KC;
    ldchunk(0, 0);
#pragma unroll 1
    for (int ci = 0; ci < NC; ci++) {
        const int st = ci & 1;
        if (ci + 1 < NC) {
            ldchunk((ci + 1) * KC, st ^ 1);
            asm volatile("cp.async.wait_group 1;" ::: "memory");
        } else {
            asm volatile("cp.async.wait_group 0;" ::: "memory");
        }
        __syncthreads();

        const uint32_t sA = pb + st * STAGE_BYTES;
        const uint32_t sB = sA + 16384;
#pragma unroll
        for (int ks = 0; ks < 2; ks++) {
            uint32_t ah[4][4], al[4][4], bh[2][4], bl[2][4];
#pragma unroll
            for (int i = 0; i < 4; i++) {
                uint32_t ro = (aRowL + i * 16) * 128 + ks * 32 + aKL;
                ldsm4(ah[i], sA + sw(ro));
                ldsm4(al[i], sA + sw(ro + 64));
            }
#pragma unroll
            for (int jp = 0; jp < 2; jp++) {
                uint32_t ro = (bRowL + jp * 16) * 128 + ks * 32 + bKL;
                ldsm4(bh[jp], sB + sw(ro));
            }
#pragma unroll
            for (int i = 0; i < 4; i++)
#pragma unroll
                for (int j = 0; j < 4; j++)
                    hmma(acc[i][j], ah[i], &bh[j >> 1][(j & 1) * 2]);
#pragma unroll
            for (int i = 0; i < 4; i++)
#pragma unroll
                for (int j = 0; j < 4; j++)
                    hmma(acc[i][j], al[i], &bh[j >> 1][(j & 1) * 2]);
#pragma unroll
            for (int jp = 0; jp < 2; jp++) {
                uint32_t ro = (bRowL + jp * 16) * 128 + ks * 32 + bKL;
                ldsm4(bl[jp], sB + sw(ro + 64));
            }
#pragma unroll
            for (int i = 0; i < 4; i++)
#pragma unroll
                for (int j = 0; j < 4; j++)
                    hmma(acc[i][j], ah[i], &bl[j >> 1][(j & 1) * 2]);
        }
        __syncthreads();
    }

    // ---- epilogue ----
    const float* bg = bias + (size_t)g * NOUT;
    const int gq = lane >> 2, tg2 = 2 * (lane & 3);
#pragma unroll
    for (int i = 0; i < 4; i++) {
        const int m0 = m_base + wm * 64 + i * 16 + gq;   // rows m0, m0+8
#pragma unroll
        for (int j = 0; j < 4; j++) {
            const int n = n0 + wn * 32 + j * 8 + tg2;
            if ((NOUT % TN != 0) && n >= NOUT) continue;
            const float b0 = bg[n], b1 = bg[n + 1];
            const float* a4 = acc[i][j];
#pragma unroll
            for (int h2 = 0; h2 < 2; h2++) {             // row m0 / m0+8
                const int m = m0 + h2 * 8;
                if (m >= m_end) continue;
                float v0 = a4[h2 * 2 + 0] + b0;
                float v1 = a4[h2 * 2 + 1] + b1;
                if (LAYER == 3) {
                    float2 v = make_float2(fast_tanh(v0), fast_tanh(v1));
                    *reinterpret_cast<float2*>(
                        out + (long)d_perm[m] * NOUT + n) = v;
                } else {
                    v0 = fmaxf(v0, 0.f); v1 = fmaxf(v1, 0.f);
                    __nv_bfloat16 h0 = __float2bfloat16(v0);
                    __nv_bfloat16 h1 = __float2bfloat16(v1);
                    uint32_t hw = (uint32_t)__bfloat16_as_ushort(h0)
                                | ((uint32_t)__bfloat16_as_ushort(h1) << 16);
                    uint32_t lw = (uint32_t)__bfloat16_as_ushort(
                                      __float2bfloat16(v0 - __bfloat162float(h0)))
                                | ((uint32_t)__bfloat16_as_ushort(
                                      __float2bfloat16(v1 - __bfloat162float(h1))) << 16);
                    *reinterpret_cast<uint32_t*>(Chi + (size_t)m * NOUT + n) = hw;
                    *reinterpret_cast<uint32_t*>(Clo + (size_t)m * NOUT + n) = lw;
                }
            }
        }
    }
}

// ---------------- launch ----------------
extern "C" void kernel_launch(void* const* d_in, const int* in_sizes, int n_in,
                              void* d_out, int out_size) {
    const float* z  = (const float*)d_in[0];
    const int*   gi = (const int*)  d_in[1];
    const float* W1 = (const float*)d_in[2];
    const float* b1 = (const float*)d_in[3];
    const float* W2 = (const float*)d_in[4];
    const float* b2 = (const float*)d_in[5];
    const float* W3 = (const float*)d_in[6];
    const float* b3 = (const float*)d_in[7];
    float* out = (float*)d_out;

    k_group<<<1, GT>>>(gi);
    k_convZ<<<(BATCH * NZ) / 256, 256>>>(z);
    k_convW<NZ, H1, H1,   1><<<dim3(H1 / 32,   NZ / 32, NGEN), dim3(32, 8)>>>(W1);
    k_convW<H1, H2, H2,   2><<<dim3(H2 / 32,   H1 / 32, NGEN), dim3(32, 8)>>>(W2);
    k_convW<H2, IMG, IMGP, 3><<<dim3(IMGP / 32, H2 / 32, NGEN), dim3(32, 8)>>>(W3);

    cudaFuncSetAttribute(mma_kernel<NZ, H1, H1, 1>,
                         cudaFuncAttributeMaxDynamicSharedMemorySize, SMEM_DYN);
    cudaFuncSetAttribute(mma_kernel<H1, H2, H2, 2>,
                         cudaFuncAttributeMaxDynamicSharedMemorySize, SMEM_DYN);
    cudaFuncSetAttribute(mma_kernel<H2, IMG, IMGP, 3>,
                         cudaFuncAttributeMaxDynamicSharedMemorySize, SMEM_DYN);

    mma_kernel<NZ, H1, H1, 1><<<dim3(MAXT, H1 / TN), 256, SMEM_DYN>>>(b1, nullptr);
    mma_kernel<H1, H2, H2, 2><<<dim3(MAXT, H2 / TN), 256, SMEM_DYN>>>(b2, nullptr);
    mma_kernel<H2, IMG, IMGP, 3><<<dim3(MAXT, IMGP / TN), 256, SMEM_DYN>>>(b3, out);
}

// round 15
// speedup vs baseline: 2.8004x; 1.5918x over previous
#include <cuda_runtime.h>
#include <cuda_fp16.h>
#include <cstdint>

// Problem constants
#define NGEN  10
#define BATCH 4096
#define NZ    128
#define H1    512
#define H2    1024
#define IMG   784
#define IMGP  896          // IMG padded to 128

// Tiling
#define TM 128             // m rows per CTA
#define TN 128             // n cols per CTA
#define KC 64              // k per stage (fp16): rows are 128B = 64 halves
#define MAXT (BATCH / TM + NGEN)        // 42
// Stage: Ah 16KB + Al 16KB + Bh 16KB
#define OFF_AH 0
#define OFF_AL 16384
#define OFF_B  32768
#define STAGE  49152
#define SMEM_DYN (2 * STAGE + 1024)

// ---------------- device scratch (no allocations; 16B-aligned) ----------------
__device__ int d_off[NGEN + 1];
__device__ int d_tileOff[NGEN + 1];
__device__ int d_perm[BATCH];

__device__ __align__(16) __half d_zH[BATCH * NZ],      d_zL[BATCH * NZ];
__device__ __align__(16) __half d_w1H[NGEN * H1 * NZ];
__device__ __align__(16) __half d_w2H[NGEN * H2 * H1];
__device__ __align__(16) __half d_w3H[NGEN * IMGP * H2];
__device__ __align__(16) __half d_h1H[BATCH * H1],     d_h1L[BATCH * H1];
__device__ __align__(16) __half d_h2H[BATCH * H2],     d_h2L[BATCH * H2];

// ---------------- helpers ----------------
__device__ __forceinline__ uint32_t s2u(const void* p) {
    uint32_t a;
    asm("{ .reg .u64 t; cvta.to.shared.u64 t, %1; cvt.u32.u64 %0, t; }"
        : "=r"(a) : "l"(p));
    return a;
}

__device__ __forceinline__ void cp16(uint32_t dst, const void* src, bool p) {
    int sz = p ? 16 : 0;   // src_size=0 -> zero-fill, no gmem read
    asm volatile("cp.async.cg.shared.global [%0], [%1], 16, %2;"
                 :: "r"(dst), "l"(src), "r"(sz));
}

__device__ __forceinline__ uint32_t sw(uint32_t o) {   // SW128 xor swizzle
    return o ^ ((o >> 3) & 0x70);
}

__device__ __forceinline__ void ldsm4(uint32_t* r, uint32_t a) {
    asm volatile("ldmatrix.sync.aligned.m8n8.x4.shared.b16 {%0,%1,%2,%3}, [%4];"
                 : "=r"(r[0]), "=r"(r[1]), "=r"(r[2]), "=r"(r[3]) : "r"(a));
}

__device__ __forceinline__ void hmma(float* d, const uint32_t* a,
                                     const uint32_t* b) {
    asm volatile(
        "mma.sync.aligned.m16n8k16.row.col.f32.f16.f16.f32 "
        "{%0,%1,%2,%3}, {%4,%5,%6,%7}, {%8,%9}, {%0,%1,%2,%3};"
        : "+f"(d[0]), "+f"(d[1]), "+f"(d[2]), "+f"(d[3])
        : "r"(a[0]), "r"(a[1]), "r"(a[2]), "r"(a[3]), "r"(b[0]), "r"(b[1]));
}

__device__ __forceinline__ float fast_tanh(float x) {
    float y; asm("tanh.approx.f32 %0, %1;" : "=f"(y) : "f"(x)); return y;
}

// ---------------- grouping: count + scan + scatter ----------------
#define GT 512
__global__ void k_group(const int* __restrict__ gi) {
    __shared__ int s_cnt[NGEN];
    __shared__ int s_cur[NGEN];
    const int t = threadIdx.x;
    if (t < NGEN) s_cnt[t] = 0;
    __syncthreads();
    int gloc[BATCH / GT];
#pragma unroll
    for (int r = 0; r < BATCH / GT; r++) {
        gloc[r] = gi[t + GT * r];
        atomicAdd(&s_cnt[gloc[r]], 1);
    }
    __syncthreads();
    if (t == 0) {
        int s = 0, tile = 0;
        for (int g = 0; g < NGEN; g++) {
            d_off[g] = s; d_tileOff[g] = tile; s_cur[g] = s;
            s += s_cnt[g];
            tile += (s_cnt[g] + TM - 1) / TM;
        }
        d_off[NGEN] = s; d_tileOff[NGEN] = tile;
    }
    __syncthreads();
#pragma unroll
    for (int r = 0; r < BATCH / GT; r++) {
        int p = atomicAdd(&s_cur[gloc[r]], 1);
        d_perm[p] = t + GT * r;   // per-row output independent => order-stable
    }
}

// ---------------- prep: z -> fp16 hi/lo ----------------
__global__ void k_convZ(const float* __restrict__ z) {
    int i = blockIdx.x * 256 + threadIdx.x;
    float v = z[i];
    __half h = __float2half_rn(v);
    d_zH[i] = h;
    d_zL[i] = __float2half_rn(v - __half2float(h));
}

// ---------------- prep: W[k][n] -> Wt_hi[n][k] (transpose, fp16 hi only) ----
template <int K, int N, int NPAD, int WSEL>
__global__ void k_convW(const float* __restrict__ W) {
    __half* Th = (WSEL == 1) ? d_w1H : (WSEL == 2) ? d_w2H : d_w3H;
    __shared__ float tile[32][33];
    const int g  = blockIdx.z;
    const int n0 = blockIdx.x * 32;
    const int k0 = blockIdx.y * 32;
    const int tx = threadIdx.x, ty = threadIdx.y;
    const float* Wg = W + (size_t)g * K * N;
#pragma unroll
    for (int i = 0; i < 4; i++) {
        int k = k0 + ty + 8 * i;
        float v = (n0 + tx < N) ? Wg[(size_t)k * N + n0 + tx] : 0.f;
        tile[ty + 8 * i][tx] = v;
    }
    __syncthreads();
#pragma unroll
    for (int i = 0; i < 4; i++) {
        int r = ty + 8 * i;                 // local n
        float v = tile[tx][r];              // = W[k0+tx][n0+r]
        Th[((size_t)g * NPAD + n0 + r) * K + k0 + tx] = __float2half_rn(v);
    }
}

// ---------------- grouped fp16 warp-MMA GEMM (2-term split) ----------------
// D = Ah*Bh + Al*Bh ; A split hi/lo fp16, B single fp16.
// Warp tile 64x32 (4x4 m16n8k16 frags); scratch resolved from LAYER in device.
template <int K, int NOUT, int NPAD, int LAYER>
__global__ __launch_bounds__(256, 2)
void mma_kernel(const float* __restrict__ bias,
                float* __restrict__ out) {
    const __half* Ahi = (LAYER == 1) ? d_zH : (LAYER == 2) ? d_h1H : d_h2H;
    const __half* Alo = (LAYER == 1) ? d_zL : (LAYER == 2) ? d_h1L : d_h2L;
    const __half* Bh  = (LAYER == 1) ? d_w1H : (LAYER == 2) ? d_w2H : d_w3H;
    __half* Chi = (LAYER == 1) ? d_h1H : d_h2H;   // unused for LAYER 3
    __half* Clo = (LAYER == 1) ? d_h1L : d_h2L;

    extern __shared__ char dyn[];
    const uint32_t pb = (s2u(dyn) + 1023u) & ~1023u;

    const int bx = blockIdx.x;
    if (bx >= d_tileOff[NGEN]) return;
    int g = 0;
#pragma unroll
    for (int i = 1; i < NGEN; i++)
        if (d_tileOff[i] <= bx) g = i;
    const int m_base = d_off[g] + (bx - d_tileOff[g]) * TM;
    const int m_end  = d_off[g + 1];
    const int n0     = blockIdx.y * TN;

    const int tid  = threadIdx.x;
    const int lane = tid & 31, wid = tid >> 5;
    const int wm   = wid & 1;        // m half (0/1): rows wm*64
    const int wn   = wid >> 1;       // n quarter (0..3): cols wn*32

    // ---- cp.async mapping: thread t -> row t>>1, granule half (t&1)*4.. ----
    const int  crow = tid >> 1;
    const int  half = tid & 1;
    bool pA = false;
    const __half* aH = Ahi;
    const __half* aL = Alo;
    { int m = m_base + crow;
      if (m < m_end) { pA = true;
          long r = (LAYER == 1) ? (long)d_perm[m] : (long)m;
          aH = Ahi + r * (long)K; aL = Alo + r * (long)K; } }
    const __half* bS = Bh + ((size_t)g * NPAD + n0 + crow) * K;
    const uint32_t dRow = crow * 128;

    auto ldchunk = [&](int kof, int st) {
        const uint32_t base = pb + st * STAGE;
#pragma unroll
        for (int q = 0; q < 4; q++) {
            const int gr = half * 4 + q;            // granule 0..7 of the row
            const uint32_t o = sw(dRow + gr * 16);
            cp16(base + OFF_AH + o, aH + kof + gr * 8, pA);
            cp16(base + OFF_AL + o, aL + kof + gr * 8, pA);
            cp16(base + OFF_B  + o, bS + kof + gr * 8, true);
        }
        asm volatile("cp.async.commit_group;" ::: "memory");
    };

    // ---- accumulators: 4 mfrags x 4 nfrags x 4 floats ----
    float acc[4][4][4];
#pragma unroll
    for (int i = 0; i < 4; i++)
#pragma unroll
        for (int j = 0; j < 4; j++)
#pragma unroll
            for (int c = 0; c < 4; c++) acc[i][j][c] = 0.f;

    // ldmatrix lane address components (within-tile; verified in R13/14)
    const int aRowL = wm * 64 + (lane & 7) + 8 * ((lane >> 3) & 1); // + i*16
    const int aKL   = (lane >> 4) * 16;                             // + ks*32
    const int bRowL = wn * 32 + (lane >> 4) * 8 + (lane & 7);       // + jp*16
    const int bKL   = ((lane >> 3) & 1) * 16;                       // + ks*32

    const int NC = K / KC;
    ldchunk(0, 0);
#pragma unroll 1
    for (int ci = 0; ci < NC; ci++) {
        const int st = ci & 1;
        if (ci + 1 < NC) {
            ldchunk((ci + 1) * KC, st ^ 1);
            asm volatile("cp.async.wait_group 1;" ::: "memory");
        } else {
            asm volatile("cp.async.wait_group 0;" ::: "memory");
        }
        __syncthreads();

        const uint32_t base = pb + st * STAGE;
#pragma unroll
        for (int ks = 0; ks < 4; ks++) {           // 4 x k16 per 64-chunk
            uint32_t ah[4][4], al[4][4], bh[2][4];
#pragma unroll
            for (int i = 0; i < 4; i++) {
                uint32_t ro = sw((aRowL + i * 16) * 128 + ks * 32 + aKL);
                ldsm4(ah[i], base + OFF_AH + ro);
                ldsm4(al[i], base + OFF_AL + ro);
            }
#pragma unroll
            for (int jp = 0; jp < 2; jp++) {
                uint32_t ro = sw((bRowL + jp * 16) * 128 + ks * 32 + bKL);
                ldsm4(bh[jp], base + OFF_B + ro);
            }
#pragma unroll
            for (int i = 0; i < 4; i++)
#pragma unroll
                for (int j = 0; j < 4; j++)
                    hmma(acc[i][j], ah[i], &bh[j >> 1][(j & 1) * 2]);
#pragma unroll
            for (int i = 0; i < 4; i++)
#pragma unroll
                for (int j = 0; j < 4; j++)
                    hmma(acc[i][j], al[i], &bh[j >> 1][(j & 1) * 2]);
        }
        __syncthreads();
    }

    // ---- epilogue ----
    const float* bg = bias + (size_t)g * NOUT;
    const int gq = lane >> 2, tg2 = 2 * (lane & 3);
#pragma unroll
    for (int i = 0; i < 4; i++) {
        const int m0 = m_base + wm * 64 + i * 16 + gq;   // rows m0, m0+8
#pragma unroll
        for (int j = 0; j < 4; j++) {
            const int n = n0 + wn * 32 + j * 8 + tg2;
            if ((NOUT % TN != 0) && n >= NOUT) continue;
            const float b0 = bg[n], b1 = bg[n + 1];
            const float* a4 = acc[i][j];
#pragma unroll
            for (int h2 = 0; h2 < 2; h2++) {             // row m0 / m0+8
                const int m = m0 + h2 * 8;
                if (m >= m_end) continue;
                float v0 = a4[h2 * 2 + 0] + b0;
                float v1 = a4[h2 * 2 + 1] + b1;
                if (LAYER == 3) {
                    float2 v = make_float2(fast_tanh(v0), fast_tanh(v1));
                    *reinterpret_cast<float2*>(
                        out + (long)d_perm[m] * NOUT + n) = v;
                } else {
                    v0 = fmaxf(v0, 0.f); v1 = fmaxf(v1, 0.f);
                    __half h0 = __float2half_rn(v0);
                    __half h1 = __float2half_rn(v1);
                    __half l0 = __float2half_rn(v0 - __half2float(h0));
                    __half l1 = __float2half_rn(v1 - __half2float(h1));
                    uint32_t hw = (uint32_t)__half_as_ushort(h0)
                                | ((uint32_t)__half_as_ushort(h1) << 16);
                    uint32_t lw = (uint32_t)__half_as_ushort(l0)
                                | ((uint32_t)__half_as_ushort(l1) << 16);
                    *reinterpret_cast<uint32_t*>(Chi + (size_t)m * NOUT + n) = hw;
                    *reinterpret_cast<uint32_t*>(Clo + (size_t)m * NOUT + n) = lw;
                }
            }
        }
    }
}

// ---------------- launch ----------------
extern "C" void kernel_launch(void* const* d_in, const int* in_sizes, int n_in,
                              void* d_out, int out_size) {
    const float* z  = (const float*)d_in[0];
    const int*   gi = (const int*)  d_in[1];
    const float* W1 = (const float*)d_in[2];
    const float* b1 = (const float*)d_in[3];
    const float* W2 = (const float*)d_in[4];
    const float* b2 = (const float*)d_in[5];
    const float* W3 = (const float*)d_in[6];
    const float* b3 = (const float*)d_in[7];
    float* out = (float*)d_out;

    k_group<<<1, GT>>>(gi);
    k_convZ<<<(BATCH * NZ) / 256, 256>>>(z);
    k_convW<NZ, H1, H1,    1><<<dim3(H1 / 32,   NZ / 32, NGEN), dim3(32, 8)>>>(W1);
    k_convW<H1, H2, H2,    2><<<dim3(H2 / 32,   H1 / 32, NGEN), dim3(32, 8)>>>(W2);
    k_convW<H2, IMG, IMGP, 3><<<dim3(IMGP / 32, H2 / 32, NGEN), dim3(32, 8)>>>(W3);

    cudaFuncSetAttribute(mma_kernel<NZ, H1, H1, 1>,
                         cudaFuncAttributeMaxDynamicSharedMemorySize, SMEM_DYN);
    cudaFuncSetAttribute(mma_kernel<H1, H2, H2, 2>,
                         cudaFuncAttributeMaxDynamicSharedMemorySize, SMEM_DYN);
    cudaFuncSetAttribute(mma_kernel<H2, IMG, IMGP, 3>,
                         cudaFuncAttributeMaxDynamicSharedMemorySize, SMEM_DYN);

    mma_kernel<NZ, H1, H1, 1><<<dim3(MAXT, H1 / TN), 256, SMEM_DYN>>>(b1, nullptr);
    mma_kernel<H1, H2, H2, 2><<<dim3(MAXT, H2 / TN), 256, SMEM_DYN>>>(b2, nullptr);
    mma_kernel<H2, IMG, IMGP, 3><<<dim3(MAXT, IMGP / TN), 256, SMEM_DYN>>>(b3, out);
}

// round 16
// speedup vs baseline: 2.9189x; 1.0423x over previous
#include <cuda_runtime.h>
#include <cuda_fp16.h>
#include <cstdint>

// Problem constants
#define NGEN  10
#define BATCH 4096
#define NZ    128
#define H1    512
#define H2    1024
#define IMG   784

// Tiling
#define TM 128             // m rows per CTA
#define TN 128             // n cols per CTA
#define KC 64              // k per stage
#define MAXT (BATCH / TM + NGEN)        // 42
// Stage: Ah 16KB + Al 16KB + B 16KB
#define OFF_AH 0
#define OFF_AL 16384
#define OFF_B  32768
#define STAGE  49152
#define SMEM_DYN (2 * STAGE + 1024)

// ---------------- device scratch (no allocations; 16B-aligned) ----------------
__device__ int d_off[NGEN + 1];
__device__ int d_tileOff[NGEN + 1];
__device__ int d_perm[BATCH];

__device__ __align__(16) __half d_zH[BATCH * NZ],      d_zL[BATCH * NZ];
__device__ __align__(16) __half d_w1H[NGEN * NZ * H1];   // [g][k][n] fp16
__device__ __align__(16) __half d_w2H[NGEN * H1 * H2];
__device__ __align__(16) __half d_w3H[NGEN * H2 * IMG];
__device__ __align__(16) __half d_h1H[BATCH * H1],     d_h1L[BATCH * H1];
__device__ __align__(16) __half d_h2H[BATCH * H2],     d_h2L[BATCH * H2];

// ---------------- helpers ----------------
__device__ __forceinline__ uint32_t s2u(const void* p) {
    uint32_t a;
    asm("{ .reg .u64 t; cvta.to.shared.u64 t, %1; cvt.u32.u64 %0, t; }"
        : "=r"(a) : "l"(p));
    return a;
}

__device__ __forceinline__ void cp16(uint32_t dst, const void* src, bool p) {
    int sz = p ? 16 : 0;   // src_size=0 -> zero-fill, no gmem read
    asm volatile("cp.async.cg.shared.global [%0], [%1], 16, %2;"
                 :: "r"(dst), "l"(src), "r"(sz));
}

__device__ __forceinline__ uint32_t sw(uint32_t o) {   // 128B-row xor swizzle
    return o ^ ((o >> 3) & 0x70);
}

__device__ __forceinline__ void ldsm4(uint32_t* r, uint32_t a) {
    asm volatile("ldmatrix.sync.aligned.m8n8.x4.shared.b16 {%0,%1,%2,%3}, [%4];"
                 : "=r"(r[0]), "=r"(r[1]), "=r"(r[2]), "=r"(r[3]) : "r"(a));
}

__device__ __forceinline__ void ldsm4t(uint32_t* r, uint32_t a) {
    asm volatile("ldmatrix.sync.aligned.m8n8.x4.trans.shared.b16 {%0,%1,%2,%3}, [%4];"
                 : "=r"(r[0]), "=r"(r[1]), "=r"(r[2]), "=r"(r[3]) : "r"(a));
}

__device__ __forceinline__ void hmma(float* d, const uint32_t* a,
                                     const uint32_t* b) {
    asm volatile(
        "mma.sync.aligned.m16n8k16.row.col.f32.f16.f16.f32 "
        "{%0,%1,%2,%3}, {%4,%5,%6,%7}, {%8,%9}, {%0,%1,%2,%3};"
        : "+f"(d[0]), "+f"(d[1]), "+f"(d[2]), "+f"(d[3])
        : "r"(a[0]), "r"(a[1]), "r"(a[2]), "r"(a[3]), "r"(b[0]), "r"(b[1]));
}

__device__ __forceinline__ float fast_tanh(float x) {
    float y; asm("tanh.approx.f32 %0, %1;" : "=f"(y) : "f"(x)); return y;
}

// ---------------- grouping: count + scan + scatter ----------------
#define GT 512
__global__ void k_group(const int* __restrict__ gi) {
    __shared__ int s_cnt[NGEN];
    __shared__ int s_cur[NGEN];
    const int t = threadIdx.x;
    if (t < NGEN) s_cnt[t] = 0;
    __syncthreads();
    int gloc[BATCH / GT];
#pragma unroll
    for (int r = 0; r < BATCH / GT; r++) {
        gloc[r] = gi[t + GT * r];
        atomicAdd(&s_cnt[gloc[r]], 1);
    }
    __syncthreads();
    if (t == 0) {
        int s = 0, tile = 0;
        for (int g = 0; g < NGEN; g++) {
            d_off[g] = s; d_tileOff[g] = tile; s_cur[g] = s;
            s += s_cnt[g];
            tile += (s_cnt[g] + TM - 1) / TM;
        }
        d_off[NGEN] = s; d_tileOff[NGEN] = tile;
    }
    __syncthreads();
#pragma unroll
    for (int r = 0; r < BATCH / GT; r++) {
        int p = atomicAdd(&s_cur[gloc[r]], 1);
        d_perm[p] = t + GT * r;   // per-row output independent => order-stable
    }
}

// ---------------- prep: z -> fp16 hi/lo ----------------
__global__ void k_convZ(const float* __restrict__ z) {
    int i = blockIdx.x * 256 + threadIdx.x;
    float v = z[i];
    __half h = __float2half_rn(v);
    d_zH[i] = h;
    d_zL[i] = __float2half_rn(v - __half2float(h));
}

// ---------------- prep: W fp32 -> fp16, same [g][k][n] layout (stream) ----
template <int TOTAL, int WSEL>
__global__ void k_convW(const float* __restrict__ W) {
    __half* Th = (WSEL == 1) ? d_w1H : (WSEL == 2) ? d_w2H : d_w3H;
    const size_t i = ((size_t)blockIdx.x * 256 + threadIdx.x) * 8;
    if (i >= TOTAL) return;
    float4 f0 = *reinterpret_cast<const float4*>(W + i);
    float4 f1 = *reinterpret_cast<const float4*>(W + i + 4);
    __half2 h0 = __floats2half2_rn(f0.x, f0.y);
    __half2 h1 = __floats2half2_rn(f0.z, f0.w);
    __half2 h2 = __floats2half2_rn(f1.x, f1.y);
    __half2 h3 = __floats2half2_rn(f1.z, f1.w);
    uint4 o;
    o.x = *reinterpret_cast<uint32_t*>(&h0);
    o.y = *reinterpret_cast<uint32_t*>(&h1);
    o.z = *reinterpret_cast<uint32_t*>(&h2);
    o.w = *reinterpret_cast<uint32_t*>(&h3);
    *reinterpret_cast<uint4*>(Th + i) = o;
}

// ---------------- grouped fp16 warp-MMA GEMM (2-term split) ----------------
// D = Ah*Bh + Al*Bh ; A [m][k] hi/lo fp16; B row-major [k][n] fp16 via
// ldmatrix.trans. Warp tile 64x32 (4x4 m16n8k16 frags).
template <int K, int NOUT, int LAYER>
__global__ __launch_bounds__(256, 2)
void mma_kernel(const float* __restrict__ bias,
                float* __restrict__ out) {
    const __half* Ahi = (LAYER == 1) ? d_zH : (LAYER == 2) ? d_h1H : d_h2H;
    const __half* Alo = (LAYER == 1) ? d_zL : (LAYER == 2) ? d_h1L : d_h2L;
    const __half* Bw  = (LAYER == 1) ? d_w1H : (LAYER == 2) ? d_w2H : d_w3H;
    __half* Chi = (LAYER == 1) ? d_h1H : d_h2H;   // unused for LAYER 3
    __half* Clo = (LAYER == 1) ? d_h1L : d_h2L;

    extern __shared__ char dyn[];
    const uint32_t pb = (s2u(dyn) + 1023u) & ~1023u;

    const int bx = blockIdx.x;
    if (bx >= d_tileOff[NGEN]) return;
    int g = 0;
#pragma unroll
    for (int i = 1; i < NGEN; i++)
        if (d_tileOff[i] <= bx) g = i;
    const int m_base = d_off[g] + (bx - d_tileOff[g]) * TM;
    const int m_end  = d_off[g + 1];
    const int n0     = blockIdx.y * TN;

    const int tid  = threadIdx.x;
    const int lane = tid & 31, wid = tid >> 5;
    const int wm   = wid & 1;        // m half (0/1): rows wm*64
    const int wn   = wid >> 1;       // n quarter (0..3): cols wn*32

    // ---- A cp.async mapping: thread t -> row t>>1, granules (t&1)*4.. ----
    const int  arow = tid >> 1;
    const int  ahlf = tid & 1;
    bool pA = false;
    const __half* aH = Ahi;
    const __half* aL = Alo;
    { int m = m_base + arow;
      if (m < m_end) { pA = true;
          long r = (LAYER == 1) ? (long)d_perm[m] : (long)m;
          aH = Ahi + r * (long)K; aL = Alo + r * (long)K; } }
    const uint32_t aRowOff = arow * 128;

    // ---- B cp.async mapping: thread t -> k-row t>>2, n-granules (t&3)*4.. ----
    const int  bkr = tid >> 2;              // 0..63 (k within stage)
    const __half* bRow = Bw + ((size_t)g * K + bkr) * NOUT + n0;
    bool pB[4];
    uint32_t bDst[4];
#pragma unroll
    for (int q = 0; q < 4; q++) {
        const int ns = (tid & 3) * 32 + q * 8;          // n start within tile
        pB[q] = (NOUT % TN == 0) || (n0 + ns < NOUT);   // NOUT%8==0
        const int h = ns >> 6, nch = (ns & 63) >> 3;
        bDst[q] = OFF_B + h * 8192 + bkr * 128 + ((nch ^ (bkr & 7)) * 16);
    }

    auto ldchunk = [&](int kof, int st) {
        const uint32_t base = pb + st * STAGE;
#pragma unroll
        for (int q = 0; q < 4; q++) {
            const int gr = ahlf * 4 + q;
            const uint32_t o = sw(aRowOff + gr * 16);
            cp16(base + OFF_AH + o, aH + kof + gr * 8, pA);
            cp16(base + OFF_AL + o, aL + kof + gr * 8, pA);
        }
        const __half* bsrc = bRow + (size_t)kof * NOUT;
#pragma unroll
        for (int q = 0; q < 4; q++)
            cp16(base + bDst[q], bsrc + (tid & 3) * 32 + q * 8, pB[q]);
        asm volatile("cp.async.commit_group;" ::: "memory");
    };

    // ---- accumulators: 4 mfrags x 4 nfrags x 4 floats ----
    float acc[4][4][4];
#pragma unroll
    for (int i = 0; i < 4; i++)
#pragma unroll
        for (int j = 0; j < 4; j++)
#pragma unroll
            for (int c = 0; c < 4; c++) acc[i][j][c] = 0.f;

    // A ldmatrix lane addressing (within-tile; verified R13-R15)
    const int aRowL = wm * 64 + (lane & 7) + 8 * ((lane >> 3) & 1); // + i*16
    const int aKL   = (lane >> 4) * 16;                             // + ks*32
    // B ldmatrix.trans lane addressing: k-row + n-column of [k][n] tile
    const int bKL   = (lane & 7) + 8 * ((lane >> 3) & 1);           // + ks*16
    const int bNL   = wn * 32 + ((lane >> 4) << 3);                 // + jp*16

    const int NC = K / KC;
    ldchunk(0, 0);
#pragma unroll 1
    for (int ci = 0; ci < NC; ci++) {
        const int st = ci & 1;
        if (ci + 1 < NC) {
            ldchunk((ci + 1) * KC, st ^ 1);
            asm volatile("cp.async.wait_group 1;" ::: "memory");
        } else {
            asm volatile("cp.async.wait_group 0;" ::: "memory");
        }
        __syncthreads();

        const uint32_t base = pb + st * STAGE;
#pragma unroll
        for (int ks = 0; ks < 4; ks++) {           // 4 x k16 per 64-chunk
            uint32_t ah[4][4], al[4][4], bh[2][4];
#pragma unroll
            for (int jp = 0; jp < 2; jp++) {
                const int kl = ks * 16 + bKL;
                const int nl = bNL + jp * 16;
                const int h = nl >> 6, nch = (nl & 63) >> 3;
                uint32_t ro = OFF_B + h * 8192 + kl * 128
                            + ((nch ^ (kl & 7)) * 16);
                ldsm4t(bh[jp], base + ro);
            }
#pragma unroll
            for (int i = 0; i < 4; i++) {
                uint32_t ro = sw((aRowL + i * 16) * 128 + ks * 32 + aKL);
                ldsm4(ah[i], base + OFF_AH + ro);
                ldsm4(al[i], base + OFF_AL + ro);
            }
#pragma unroll
            for (int i = 0; i < 4; i++)
#pragma unroll
                for (int j = 0; j < 4; j++)
                    hmma(acc[i][j], ah[i], &bh[j >> 1][(j & 1) * 2]);
#pragma unroll
            for (int i = 0; i < 4; i++)
#pragma unroll
                for (int j = 0; j < 4; j++)
                    hmma(acc[i][j], al[i], &bh[j >> 1][(j & 1) * 2]);
        }
        __syncthreads();
    }

    // ---- epilogue ----
    const float* bg = bias + (size_t)g * NOUT;
    const int gq = lane >> 2, tg2 = 2 * (lane & 3);
#pragma unroll
    for (int i = 0; i < 4; i++) {
        const int m0 = m_base + wm * 64 + i * 16 + gq;   // rows m0, m0+8
#pragma unroll
        for (int j = 0; j < 4; j++) {
            const int n = n0 + wn * 32 + j * 8 + tg2;
            if ((NOUT % TN != 0) && n >= NOUT) continue;
            const float b0 = bg[n], b1 = bg[n + 1];
            const float* a4 = acc[i][j];
#pragma unroll
            for (int h2 = 0; h2 < 2; h2++) {             // row m0 / m0+8
                const int m = m0 + h2 * 8;
                if (m >= m_end) continue;
                float v0 = a4[h2 * 2 + 0] + b0;
                float v1 = a4[h2 * 2 + 1] + b1;
                if (LAYER == 3) {
                    float2 v = make_float2(fast_tanh(v0), fast_tanh(v1));
                    *reinterpret_cast<float2*>(
                        out + (long)d_perm[m] * NOUT + n) = v;
                } else {
                    v0 = fmaxf(v0, 0.f); v1 = fmaxf(v1, 0.f);
                    __half h0 = __float2half_rn(v0);
                    __half h1 = __float2half_rn(v1);
                    __half l0 = __float2half_rn(v0 - __half2float(h0));
                    __half l1 = __float2half_rn(v1 - __half2float(h1));
                    uint32_t hw = (uint32_t)__half_as_ushort(h0)
                                | ((uint32_t)__half_as_ushort(h1) << 16);
                    uint32_t lw = (uint32_t)__half_as_ushort(l0)
                                | ((uint32_t)__half_as_ushort(l1) << 16);
                    *reinterpret_cast<uint32_t*>(Chi + (size_t)m * NOUT + n) = hw;
                    *reinterpret_cast<uint32_t*>(Clo + (size_t)m * NOUT + n) = lw;
                }
            }
        }
    }
}

// ---------------- launch ----------------
extern "C" void kernel_launch(void* const* d_in, const int* in_sizes, int n_in,
                              void* d_out, int out_size) {
    const float* z  = (const float*)d_in[0];
    const int*   gi = (const int*)  d_in[1];
    const float* W1 = (const float*)d_in[2];
    const float* b1 = (const float*)d_in[3];
    const float* W2 = (const float*)d_in[4];
    const float* b2 = (const float*)d_in[5];
    const float* W3 = (const float*)d_in[6];
    const float* b3 = (const float*)d_in[7];
    float* out = (float*)d_out;

    k_group<<<1, GT>>>(gi);
    k_convZ<<<(BATCH * NZ) / 256, 256>>>(z);
    k_convW<NGEN * NZ * H1, 1><<<NGEN * NZ * H1 / 2048, 256>>>(W1);
    k_convW<NGEN * H1 * H2, 2><<<NGEN * H1 * H2 / 2048, 256>>>(W2);
    k_convW<NGEN * H2 * IMG, 3><<<NGEN * H2 * IMG / 2048, 256>>>(W3);

    cudaFuncSetAttribute(mma_kernel<NZ, H1, 1>,
                         cudaFuncAttributeMaxDynamicSharedMemorySize, SMEM_DYN);
    cudaFuncSetAttribute(mma_kernel<H1, H2, 2>,
                         cudaFuncAttributeMaxDynamicSharedMemorySize, SMEM_DYN);
    cudaFuncSetAttribute(mma_kernel<H2, IMG, 3>,
                         cudaFuncAttributeMaxDynamicSharedMemorySize, SMEM_DYN);

    mma_kernel<NZ, H1, 1><<<dim3(MAXT, H1 / TN), 256, SMEM_DYN>>>(b1, nullptr);
    mma_kernel<H1, H2, 2><<<dim3(MAXT, H2 / TN), 256, SMEM_DYN>>>(b2, nullptr);
    mma_kernel<H2, IMG, 3><<<dim3(MAXT, (IMG + TN - 1) / TN), 256, SMEM_DYN>>>(b3, out);
}

// round 17
// speedup vs baseline: 4.1728x; 1.4296x over previous
#include <cuda_runtime.h>
#include <cuda_fp16.h>
#include <cstdint>

// Problem constants
#define NGEN  10
#define BATCH 4096
#define NZ    128
#define H1    512
#define H2    1024
#define IMG   784

// Tiling
#define TM 128             // m rows per CTA
#define TN 128             // n cols per CTA
#define KC 64              // k per stage
#define MAXT (BATCH / TM + NGEN)        // 42
// Stage: A 16KB + B 16KB; 3 stages
#define OFF_A  0
#define OFF_B  16384
#define STAGE  32768
#define NSTAGE 3
#define SMEM_DYN (NSTAGE * STAGE + 1024)

// ---------------- device scratch (no allocations; 16B-aligned) ----------------
__device__ int d_off[NGEN + 1];
__device__ int d_tileOff[NGEN + 1];
__device__ int d_perm[BATCH];

__device__ __align__(16) __half d_zH[BATCH * NZ];
__device__ __align__(16) __half d_w1H[NGEN * NZ * H1];   // [g][k][n] fp16
__device__ __align__(16) __half d_w2H[NGEN * H1 * H2];
__device__ __align__(16) __half d_w3H[NGEN * H2 * IMG];
__device__ __align__(16) __half d_h1H[BATCH * H1];
__device__ __align__(16) __half d_h2H[BATCH * H2];

// ---------------- helpers ----------------
__device__ __forceinline__ uint32_t s2u(const void* p) {
    uint32_t a;
    asm("{ .reg .u64 t; cvta.to.shared.u64 t, %1; cvt.u32.u64 %0, t; }"
        : "=r"(a) : "l"(p));
    return a;
}

__device__ __forceinline__ void cp16(uint32_t dst, const void* src, bool p) {
    int sz = p ? 16 : 0;   // src_size=0 -> zero-fill, no gmem read
    asm volatile("cp.async.cg.shared.global [%0], [%1], 16, %2;"
                 :: "r"(dst), "l"(src), "r"(sz));
}

__device__ __forceinline__ uint32_t sw(uint32_t o) {   // 128B-row xor swizzle
    return o ^ ((o >> 3) & 0x70);
}

__device__ __forceinline__ void ldsm4(uint32_t* r, uint32_t a) {
    asm volatile("ldmatrix.sync.aligned.m8n8.x4.shared.b16 {%0,%1,%2,%3}, [%4];"
                 : "=r"(r[0]), "=r"(r[1]), "=r"(r[2]), "=r"(r[3]) : "r"(a));
}

__device__ __forceinline__ void ldsm4t(uint32_t* r, uint32_t a) {
    asm volatile("ldmatrix.sync.aligned.m8n8.x4.trans.shared.b16 {%0,%1,%2,%3}, [%4];"
                 : "=r"(r[0]), "=r"(r[1]), "=r"(r[2]), "=r"(r[3]) : "r"(a));
}

__device__ __forceinline__ void hmma(float* d, const uint32_t* a,
                                     const uint32_t* b) {
    asm volatile(
        "mma.sync.aligned.m16n8k16.row.col.f32.f16.f16.f32 "
        "{%0,%1,%2,%3}, {%4,%5,%6,%7}, {%8,%9}, {%0,%1,%2,%3};"
        : "+f"(d[0]), "+f"(d[1]), "+f"(d[2]), "+f"(d[3])
        : "r"(a[0]), "r"(a[1]), "r"(a[2]), "r"(a[3]), "r"(b[0]), "r"(b[1]));
}

__device__ __forceinline__ float fast_tanh(float x) {
    float y; asm("tanh.approx.f32 %0, %1;" : "=f"(y) : "f"(x)); return y;
}

// ---------------- grouping: count + scan + scatter ----------------
#define GT 512
__global__ void k_group(const int* __restrict__ gi) {
    __shared__ int s_cnt[NGEN];
    __shared__ int s_cur[NGEN];
    const int t = threadIdx.x;
    if (t < NGEN) s_cnt[t] = 0;
    __syncthreads();
    int gloc[BATCH / GT];
#pragma unroll
    for (int r = 0; r < BATCH / GT; r++) {
        gloc[r] = gi[t + GT * r];
        atomicAdd(&s_cnt[gloc[r]], 1);
    }
    __syncthreads();
    if (t == 0) {
        int s = 0, tile = 0;
        for (int g = 0; g < NGEN; g++) {
            d_off[g] = s; d_tileOff[g] = tile; s_cur[g] = s;
            s += s_cnt[g];
            tile += (s_cnt[g] + TM - 1) / TM;
        }
        d_off[NGEN] = s; d_tileOff[NGEN] = tile;
    }
    __syncthreads();
#pragma unroll
    for (int r = 0; r < BATCH / GT; r++) {
        int p = atomicAdd(&s_cur[gloc[r]], 1);
        d_perm[p] = t + GT * r;   // per-row output independent => order-stable
    }
}

// ---------------- prep: z -> fp16 ----------------
__global__ void k_convZ(const float* __restrict__ z) {
    int i = blockIdx.x * 256 + threadIdx.x;
    d_zH[i] = __float2half_rn(z[i]);
}

// ---------------- prep: W fp32 -> fp16, same [g][k][n] layout (stream) ----
template <int TOTAL, int WSEL>
__global__ void k_convW(const float* __restrict__ W) {
    __half* Th = (WSEL == 1) ? d_w1H : (WSEL == 2) ? d_w2H : d_w3H;
    const size_t i = ((size_t)blockIdx.x * 256 + threadIdx.x) * 16;
    if (i >= TOTAL) return;
#pragma unroll
    for (int u = 0; u < 2; u++) {
        float4 f0 = *reinterpret_cast<const float4*>(W + i + u * 8);
        float4 f1 = *reinterpret_cast<const float4*>(W + i + u * 8 + 4);
        __half2 h0 = __floats2half2_rn(f0.x, f0.y);
        __half2 h1 = __floats2half2_rn(f0.z, f0.w);
        __half2 h2 = __floats2half2_rn(f1.x, f1.y);
        __half2 h3 = __floats2half2_rn(f1.z, f1.w);
        uint4 o;
        o.x = *reinterpret_cast<uint32_t*>(&h0);
        o.y = *reinterpret_cast<uint32_t*>(&h1);
        o.z = *reinterpret_cast<uint32_t*>(&h2);
        o.w = *reinterpret_cast<uint32_t*>(&h3);
        *reinterpret_cast<uint4*>(Th + i + u * 8) = o;
    }
}

// ---------------- grouped fp16 warp-MMA GEMM (pure fp16, fp32 accum) --------
// D = A*B ; A [m][k] fp16; B row-major [k][n] fp16 via ldmatrix.trans.
// Warp tile 64x32 (4x4 m16n8k16 frags). 3-stage, 1 barrier/chunk.
template <int K, int NOUT, int LAYER>
__global__ __launch_bounds__(256, 2)
void mma_kernel(const float* __restrict__ bias,
                float* __restrict__ out) {
    const __half* Ain = (LAYER == 1) ? d_zH : (LAYER == 2) ? d_h1H : d_h2H;
    const __half* Bw  = (LAYER == 1) ? d_w1H : (LAYER == 2) ? d_w2H : d_w3H;
    __half* Cst = (LAYER == 1) ? d_h1H : d_h2H;   // unused for LAYER 3

    extern __shared__ char dyn[];
    const uint32_t pb = (s2u(dyn) + 1023u) & ~1023u;

    const int bx = blockIdx.x;
    if (bx >= d_tileOff[NGEN]) return;
    int g = 0;
#pragma unroll
    for (int i = 1; i < NGEN; i++)
        if (d_tileOff[i] <= bx) g = i;
    const int m_base = d_off[g] + (bx - d_tileOff[g]) * TM;
    const int m_end  = d_off[g + 1];
    const int n0     = blockIdx.y * TN;

    const int tid  = threadIdx.x;
    const int lane = tid & 31, wid = tid >> 5;
    const int wm   = wid & 1;        // m half (0/1): rows wm*64
    const int wn   = wid >> 1;       // n quarter (0..3): cols wn*32

    // ---- A cp.async mapping: thread t -> row t>>1, granules (t&1)*4.. ----
    const int  arow = tid >> 1;
    const int  ahlf = tid & 1;
    bool pA = false;
    const __half* aS = Ain;
    { int m = m_base + arow;
      if (m < m_end) { pA = true;
          long r = (LAYER == 1) ? (long)d_perm[m] : (long)m;
          aS = Ain + r * (long)K; } }
    const uint32_t aRowOff = arow * 128;

    // ---- B cp.async mapping: thread t -> k-row t>>2, n-granules (t&3)*4.. ----
    const int  bkr = tid >> 2;              // 0..63 (k within stage)
    const __half* bRow = Bw + ((size_t)g * K + bkr) * NOUT + n0;
    bool pB[4];
    uint32_t bDst[4];
#pragma unroll
    for (int q = 0; q < 4; q++) {
        const int ns = (tid & 3) * 32 + q * 8;          // n start within tile
        pB[q] = (NOUT % TN == 0) || (n0 + ns < NOUT);   // NOUT%8==0
        const int h = ns >> 6, nch = (ns & 63) >> 3;
        bDst[q] = OFF_B + h * 8192 + bkr * 128 + ((nch ^ (bkr & 7)) * 16);
    }

    auto ldchunk = [&](int kof, int st) {
        const uint32_t base = pb + st * STAGE;
#pragma unroll
        for (int q = 0; q < 4; q++) {
            const int gr = ahlf * 4 + q;
            cp16(base + OFF_A + sw(aRowOff + gr * 16), aS + kof + gr * 8, pA);
        }
        const __half* bsrc = bRow + (size_t)kof * NOUT;
#pragma unroll
        for (int q = 0; q < 4; q++)
            cp16(base + bDst[q], bsrc + (tid & 3) * 32 + q * 8, pB[q]);
        asm volatile("cp.async.commit_group;" ::: "memory");
    };

    // ---- accumulators: 4 mfrags x 4 nfrags x 4 floats ----
    float acc[4][4][4];
#pragma unroll
    for (int i = 0; i < 4; i++)
#pragma unroll
        for (int j = 0; j < 4; j++)
#pragma unroll
            for (int c = 0; c < 4; c++) acc[i][j][c] = 0.f;

    // A ldmatrix lane addressing (within-tile; verified R13-R16)
    const int aRowL = wm * 64 + (lane & 7) + 8 * ((lane >> 3) & 1); // + i*16
    const int aKL   = (lane >> 4) * 16;                             // + ks*32
    // B ldmatrix.trans lane addressing: k-row + n-column of [k][n] tile
    const int bKL   = (lane & 7) + 8 * ((lane >> 3) & 1);           // + ks*16
    const int bNL   = wn * 32 + ((lane >> 4) << 3);                 // + jp*16

    const int NC = K / KC;
    // Prologue: fill stages 0 and 1 (NC >= 2 for all layers)
    ldchunk(0, 0);
    ldchunk(KC, 1);

    int st = 0;
#pragma unroll 1
    for (int ci = 0; ci < NC; ci++) {
        if (ci + 1 < NC) {
            asm volatile("cp.async.wait_group 1;" ::: "memory");
        } else {
            asm volatile("cp.async.wait_group 0;" ::: "memory");
        }
        __syncthreads();   // chunk ci ready; all reads of stage wst done

        if (ci + 2 < NC) {
            int wst = st + 2; if (wst >= NSTAGE) wst -= NSTAGE;
            ldchunk((ci + 2) * KC, wst);
        }

        const uint32_t base = pb + st * STAGE;
#pragma unroll
        for (int ks = 0; ks < 4; ks++) {           // 4 x k16 per 64-chunk
            uint32_t ah[4][4], bh[2][4];
#pragma unroll
            for (int jp = 0; jp < 2; jp++) {
                const int kl = ks * 16 + bKL;
                const int nl = bNL + jp * 16;
                const int h = nl >> 6, nch = (nl & 63) >> 3;
                uint32_t ro = OFF_B + h * 8192 + kl * 128
                            + ((nch ^ (kl & 7)) * 16);
                ldsm4t(bh[jp], base + ro);
            }
#pragma unroll
            for (int i = 0; i < 4; i++) {
                uint32_t ro = sw((aRowL + i * 16) * 128 + ks * 32 + aKL);
                ldsm4(ah[i], base + OFF_A + ro);
            }
#pragma unroll
            for (int i = 0; i < 4; i++)
#pragma unroll
                for (int j = 0; j < 4; j++)
                    hmma(acc[i][j], ah[i], &bh[j >> 1][(j & 1) * 2]);
        }
        st = st + 1; if (st >= NSTAGE) st -= NSTAGE;
    }

    // ---- epilogue ----
    const float* bg = bias + (size_t)g * NOUT;
    const int gq = lane >> 2, tg2 = 2 * (lane & 3);
#pragma unroll
    for (int i = 0; i < 4; i++) {
        const int m0 = m_base + wm * 64 + i * 16 + gq;   // rows m0, m0+8
#pragma unroll
        for (int j = 0; j < 4; j++) {
            const int n = n0 + wn * 32 + j * 8 + tg2;
            if ((NOUT % TN != 0) && n >= NOUT) continue;
            const float b0 = bg[n], b1 = bg[n + 1];
            const float* a4 = acc[i][j];
#pragma unroll
            for (int h2 = 0; h2 < 2; h2++) {             // row m0 / m0+8
                const int m = m0 + h2 * 8;
                if (m >= m_end) continue;
                float v0 = a4[h2 * 2 + 0] + b0;
                float v1 = a4[h2 * 2 + 1] + b1;
                if (LAYER == 3) {
                    float2 v = make_float2(fast_tanh(v0), fast_tanh(v1));
                    *reinterpret_cast<float2*>(
                        out + (long)d_perm[m] * NOUT + n) = v;
                } else {
                    __half2 h = __floats2half2_rn(fmaxf(v0, 0.f),
                                                  fmaxf(v1, 0.f));
                    *reinterpret_cast<uint32_t*>(Cst + (size_t)m * NOUT + n)
                        = *reinterpret_cast<uint32_t*>(&h);
                }
            }
        }
    }
}

// ---------------- launch ----------------
extern "C" void kernel_launch(void* const* d_in, const int* in_sizes, int n_in,
                              void* d_out, int out_size) {
    const float* z  = (const float*)d_in[0];
    const int*   gi = (const int*)  d_in[1];
    const float* b1 = (const float*)d_in[3];
    const float* b2 = (const float*)d_in[5];
    const float* b3 = (const float*)d_in[7];
    const float* W1 = (const float*)d_in[2];
    const float* W2 = (const float*)d_in[4];
    const float* W3 = (const float*)d_in[6];
    float* out = (float*)d_out;

    k_group<<<1, GT>>>(gi);
    k_convZ<<<(BATCH * NZ) / 256, 256>>>(z);
    k_convW<NGEN * NZ * H1, 1><<<NGEN * NZ * H1 / 4096, 256>>>(W1);
    k_convW<NGEN * H1 * H2, 2><<<NGEN * H1 * H2 / 4096, 256>>>(W2);
    k_convW<NGEN * H2 * IMG, 3><<<NGEN * H2 * IMG / 4096, 256>>>(W3);

    cudaFuncSetAttribute(mma_kernel<NZ, H1, 1>,
                         cudaFuncAttributeMaxDynamicSharedMemorySize, SMEM_DYN);
    cudaFuncSetAttribute(mma_kernel<H1, H2, 2>,
                         cudaFuncAttributeMaxDynamicSharedMemorySize, SMEM_DYN);
    cudaFuncSetAttribute(mma_kernel<H2, IMG, 3>,
                         cudaFuncAttributeMaxDynamicSharedMemorySize, SMEM_DYN);

    mma_kernel<NZ, H1, 1><<<dim3(MAXT, H1 / TN), 256, SMEM_DYN>>>(b1, nullptr);
    mma_kernel<H1, H2, 2><<<dim3(MAXT, H2 / TN), 256, SMEM_DYN>>>(b2, nullptr);
    mma_kernel<H2, IMG, 3><<<dim3(MAXT, (IMG + TN - 1) / TN), 256, SMEM_DYN>>>(b3, out);
}